// round 15
// baseline (speedup 1.0000x reference)
#include <cuda_runtime.h>
#include <math.h>
#include <stdint.h>

#define B_     128
#define HID_   512
#define NG_    2048
#define VOCAB_ 1000
#define VTOT_  3048
#define ROWS_  3072
#define T_     256
#define GRID_  148
#define NTHR   256
#define XCTAS  128           // 32 M-tiles (96 rows) x 4 K-splits

#define OUT_H  (B_*T_*VOCAB_)
#define OUT_C  (OUT_H + B_*HID_)

// ---------------- device scratch ----------------
__device__ __align__(16) float g_E2[VOCAB_*NG_];     // [v][u][4]: i,f,g,o
__device__ __align__(16) float g_base[NG_*B_];       // col-major [gatecol][r]
__device__ __align__(16) float g_hhi[B_*HID_];       // tf32-hi of h
__device__ __align__(16) float g_hlo[B_*HID_];       // tf32-lo of h
__device__ __align__(16) float g_part[4*ROWS_*B_];   // [k][row][r]
__device__ __align__(16) unsigned long long g_mid[2][B_*8];  // slotted argmax
__device__ __align__(16) unsigned g_dmid[2][B_*8];           // slotted done counters
__device__ unsigned g_bar;

__device__ __forceinline__ float tf32_rd(float x){
  uint32_t u; asm("cvt.rna.tf32.f32 %0, %1;" : "=r"(u) : "f"(x));
  return __uint_as_float(u);
}
__device__ __forceinline__ unsigned fkey(float x){
  unsigned u = __float_as_uint(x);
  return (u & 0x80000000u) ? ~u : (u | 0x80000000u);
}
__device__ __forceinline__ void mma_tf32(float* d, const uint32_t* a, const uint32_t* b){
  asm volatile("mma.sync.aligned.m16n8k8.row.col.f32.tf32.tf32.f32 "
    "{%0,%1,%2,%3}, {%4,%5,%6,%7}, {%8,%9}, {%0,%1,%2,%3};"
    : "+f"(d[0]), "+f"(d[1]), "+f"(d[2]), "+f"(d[3])
    : "r"(a[0]), "r"(a[1]), "r"(a[2]), "r"(a[3]), "r"(b[0]), "r"(b[1]));
}
#define DOT4(acc, a, b) acc = fmaf((a).x,(b).x, fmaf((a).y,(b).y, fmaf((a).z,(b).z, fmaf((a).w,(b).w,(acc)))))

// ---- MUFU-free transcendentals (FMA pipe only) ----
__device__ __forceinline__ float ex2f(float x){
  float xr = rintf(x);
  float f = x - xr;
  float p = 1.5252734e-5f;
  p = fmaf(p, f, 1.5403530e-4f);
  p = fmaf(p, f, 1.3333558e-3f);
  p = fmaf(p, f, 9.6181291e-3f);
  p = fmaf(p, f, 5.5504109e-2f);
  p = fmaf(p, f, 2.4022651e-1f);
  p = fmaf(p, f, 6.9314718e-1f);
  p = fmaf(p, f, 1.0f);
  return __int_as_float(__float_as_int(p) + ((int)xr << 23));
}
__device__ __forceinline__ float rcpf(float d){
  float r = __int_as_float((int)(0x7EF127EAu - (unsigned)__float_as_int(d)));
  r = r * fmaf(-d, r, 2.f);
  r = r * fmaf(-d, r, 2.f);
  r = r * fmaf(-d, r, 2.f);
  return r;
}
#define L2E 1.4426950408889634f

__device__ __forceinline__ void lstm_cell(float gi, float gf, float gg, float go,
                                          float& c, float& hn){
  gi = fminf(fmaxf(gi, -15.f), 15.f);
  gf = fminf(fmaxf(gf, -15.f), 15.f);
  gg = fminf(fmaxf(gg, -15.f), 15.f);
  go = fminf(fmaxf(go, -15.f), 15.f);
  float ei = ex2f(-L2E*gi), ef = ex2f(-L2E*gf);
  float eo = ex2f(-L2E*go), eg = ex2f(-2.f*L2E*gg);
  float di = 1.f+ei, df = 1.f+ef, dv = 1.f+eo, dg = 1.f+eg;
  float q1 = di*df, q2 = dv*dg;
  float rp = rcpf(q1*q2);
  float si = rp*df*q2;
  float sf = rp*di*q2;
  float so = rp*q1*dg;
  float tg = (1.f-eg)*(rp*q1*dv);
  float cn = fmaf(sf, c, si*tg);
  c = cn;
  float tc = fminf(fmaxf(cn, -15.f), 15.f);
  float ec = ex2f(-2.f*L2E*tc);
  hn = so * (1.f-ec) * rcpf(1.f+ec);
}

// ---------------- prologue 1: E2 = embed @ Wih_emb^T ----------------
__global__ void __launch_bounds__(256) k_E(const float* __restrict__ emb,
                                           const float* __restrict__ Wih){
  __shared__ float As[16*68], Bs[16*68];
  const int tid = threadIdx.x;
  const int tx = tid & 15, ty = tid >> 4;
  const int c0 = blockIdx.x * 64, v0 = blockIdx.y * 64;
  float acc[4][4];
#pragma unroll
  for (int i=0;i<4;++i)
#pragma unroll
    for (int j=0;j<4;++j) acc[i][j] = 0.f;

  const int rr = tid >> 2, kq = tid & 3;
  for (int kc = 0; kc < 512; kc += 16){
    int v = v0 + rr; if (v >= VOCAB_) v = VOCAB_ - 1;
    float4 a = __ldg((const float4*)(emb + (size_t)v*512 + kc + 4*kq));
    As[(4*kq+0)*68 + rr] = a.x; As[(4*kq+1)*68 + rr] = a.y;
    As[(4*kq+2)*68 + rr] = a.z; As[(4*kq+3)*68 + rr] = a.w;
    int g = c0 + rr;
    float4 b = __ldg((const float4*)(Wih + (size_t)g*1024 + 512 + kc + 4*kq));
    Bs[(4*kq+0)*68 + rr] = b.x; Bs[(4*kq+1)*68 + rr] = b.y;
    Bs[(4*kq+2)*68 + rr] = b.z; Bs[(4*kq+3)*68 + rr] = b.w;
    __syncthreads();
#pragma unroll
    for (int k = 0; k < 16; ++k){
      float4 av = *(const float4*)&As[k*68 + ty*4];
      float4 bv = *(const float4*)&Bs[k*68 + tx*4];
      float ai[4] = {av.x, av.y, av.z, av.w};
      float bj[4] = {bv.x, bv.y, bv.z, bv.w};
#pragma unroll
      for (int i=0;i<4;++i)
#pragma unroll
        for (int j=0;j<4;++j) acc[i][j] = fmaf(ai[i], bj[j], acc[i][j]);
    }
    __syncthreads();
  }
  for (int i=0;i<4;++i){
    int v = v0 + ty*4 + i;
    if (v < VOCAB_)
      for (int j=0;j<4;++j){
        int c = c0 + tx*4 + j;
        g_E2[((size_t)v*512 + (c & 511))*4 + (c >> 9)] = acc[i][j];
      }
  }
}

// ---------------- prologue 2: g_base (exact fp32) ----------------
__global__ void __launch_bounds__(256) k_base(const float* __restrict__ Wih,
                                              const float* __restrict__ bih,
                                              const float* __restrict__ bhh,
                                              const float* __restrict__ ctx){
  __shared__ float xs[128*68], wsm[16*68];
  const int tid = threadIdx.x, blk = blockIdx.x;
  const int tx = tid & 7, ty = tid >> 3, r0 = ty*4;
  const int gc0 = blk*16 + 2*tx, gc1 = gc0 + 1;
  float acc[4][2];
#pragma unroll
  for (int i=0;i<4;++i){ acc[i][0]=0.f; acc[i][1]=0.f; }

  for (int kc = 0; kc < 512; kc += 64){
    for (int p = 0; p < 8; ++p){
      int lin = tid + p*256; int r = lin >> 4, kq2 = lin & 15;
      *(float4*)&xs[r*68 + 4*kq2] = __ldg((const float4*)(ctx + (size_t)r*512 + kc + 4*kq2));
    }
    { int cc = tid >> 4, kq2 = tid & 15;
      *(float4*)&wsm[cc*68 + 4*kq2] =
        __ldg((const float4*)(Wih + (size_t)(blk*16+cc)*1024 + kc + 4*kq2)); }
    __syncthreads();
#pragma unroll
    for (int k4 = 0; k4 < 16; ++k4){
      int kl = 4*k4;
      float4 w0 = *(const float4*)&wsm[(2*tx)*68 + kl];
      float4 w1 = *(const float4*)&wsm[(2*tx+1)*68 + kl];
#pragma unroll
      for (int i=0;i<4;++i){
        float4 h4 = *(const float4*)&xs[(r0+i)*68 + kl];
        DOT4(acc[i][0], h4, w0); DOT4(acc[i][1], h4, w1);
      }
    }
    __syncthreads();
  }
  float bb0 = __ldg(bih+gc0) + __ldg(bhh+gc0);
  float bb1 = __ldg(bih+gc1) + __ldg(bhh+gc1);
  for (int i=0;i<4;++i){
    g_base[(size_t)gc0*B_ + r0+i] = acc[i][0] + bb0;
    g_base[(size_t)gc1*B_ + r0+i] = acc[i][1] + bb1;
  }
}

// ---------------- prologue 3 ----------------
__global__ void k_init(const float* __restrict__ ctx, const int* __restrict__ sid){
  int idx = blockIdx.x*blockDim.x + threadIdx.x;
  if (idx < B_*HID_){
    float x = ctx[idx];
    float hi = tf32_rd(x);
    g_hhi[idx] = hi;
    g_hlo[idx] = tf32_rd(x - hi);
  }
  if (idx < B_*8){
    // slot 0 of each row carries the start token for step 0; others 0
    g_mid[0][idx] = ((idx & 7) == 0)
      ? ((1ull << 32) | (unsigned)((VOCAB_-1) - *sid)) : 0ull;
    g_mid[1][idx] = 0ull;
    g_dmid[0][idx] = 0u;
    g_dmid[1][idx] = 0u;
  }
  if (idx == 0) g_bar = 0u;
}

// ---------------- grid barrier ----------------
__device__ __forceinline__ void gbar(unsigned target){
  __syncthreads();
  if (threadIdx.x == 0){
    __threadfence();
    atomicAdd(&g_bar, 1u);
    while (*(volatile unsigned*)&g_bar < target) { }
    __threadfence();
  }
  __syncthreads();
}

// ---------------- persistent kernel ----------------
// smem float offsets
#define SA_H   0                 // A hi frag-packed: 96*128 = 12288
#define SA_L   12288             // A lo
#define SB_H   24576             // B hi tile [128][68] = 8704
#define SB_L   33280             // B lo tile
#define S_LS   41984             // 8*128 floats
#define SMW_   43008             // 172032 bytes

__global__ void __launch_bounds__(NTHR, 1)
k_persist(const float* __restrict__ Whh, const float* __restrict__ Wout,
          const float* __restrict__ bout, float* __restrict__ out){
  extern __shared__ float sm[];
  float* Ah = sm + SA_H;
  float* Al = sm + SA_L;
  float* Bh = sm + SB_H;
  float* Bl = sm + SB_L;
  float* Ls = sm + S_LS;

  const int cta = blockIdx.x, tid = threadIdx.x;
  const int wid = tid >> 5, lane = tid & 31;
  const bool isX = (cta < XCTAS);
  const int mtile = cta >> 2, kidx = cta & 3, kbase = kidx*128;
  const int wm = wid >> 2, wn = wid & 3;          // warp tile 48M x 32N

  // ---- stage A (weights hi/lo, fragment-packed) once ----
  if (isX){
    for (int lin = tid; lin < 3072; lin += NTHR){
      int ml = lin >> 5, q = lin & 31;
      int gm = mtile*96 + ml;
      float4 w = make_float4(0.f,0.f,0.f,0.f);
      if (gm < NG_)        w = __ldg((const float4*)(Whh  + (size_t)gm*HID_ + kbase + q*4));
      else if (gm < VTOT_) w = __ldg((const float4*)(Wout + (size_t)(gm-NG_)*HID_ + kbase + q*4));
      int f = (ml >> 4)*16 + (q >> 1);
      int ofs = f*128 + (ml & 7)*16 + ((ml >> 3) & 1) + 2*(q & 1);
      float hi;
      hi = tf32_rd(w.x); Ah[ofs+ 0] = hi; Al[ofs+ 0] = tf32_rd(w.x - hi);
      hi = tf32_rd(w.y); Ah[ofs+ 4] = hi; Al[ofs+ 4] = tf32_rd(w.y - hi);
      hi = tf32_rd(w.z); Ah[ofs+ 8] = hi; Al[ofs+ 8] = tf32_rd(w.z - hi);
      hi = tf32_rd(w.w); Ah[ofs+12] = hi; Al[ofs+12] = tf32_rd(w.w - hi);
    }
  }
  __syncthreads();

  float cr0 = 0.f, cr1 = 0.f;
  const int yi0 = cta*NTHR + tid;                 // < 37888
  const int yi1 = yi0 + GRID_*NTHR;               // yi1 & 127 == yi0 & 127
  const bool v1ok = (yi1 < B_*HID_);

  unsigned bt = 0;
  for (int m = 0; m <= T_; ++m){
    // ================ phase X: 3xTF32 mma.sync ================
    if (isX){
      float acc[12][4];
#pragma unroll
      for (int i=0;i<12;++i)
#pragma unroll
        for (int j=0;j<4;++j) acc[i][j] = 0.f;

      for (int ch = 0; ch < 2; ++ch){
        for (int lin = tid; lin < 2048; lin += NTHR){
          int r = lin >> 4, q = lin & 15;
          float4 h = __ldcg((const float4*)(g_hhi + (size_t)r*HID_ + kbase + ch*64 + q*4));
          float4 l = __ldcg((const float4*)(g_hlo + (size_t)r*HID_ + kbase + ch*64 + q*4));
          *(float4*)&Bh[r*68 + q*4] = h;
          *(float4*)&Bl[r*68 + q*4] = l;
        }
        __syncthreads();
#pragma unroll 2
        for (int ks = 0; ks < 8; ++ks){
          uint32_t bh[4][2], bl[4][2];
          int kk = ks*8 + (lane & 3);
#pragma unroll
          for (int ni = 0; ni < 4; ++ni){
            int n = wn*32 + ni*8 + (lane >> 2);
            bh[ni][0] = __float_as_uint(Bh[n*68 + kk]);
            bh[ni][1] = __float_as_uint(Bh[n*68 + kk + 4]);
            bl[ni][0] = __float_as_uint(Bl[n*68 + kk]);
            bl[ni][1] = __float_as_uint(Bl[n*68 + kk + 4]);
          }
          uint4 ahv[3], alv[3];
#pragma unroll
          for (int mi = 0; mi < 3; ++mi){
            int f = (wm*3 + mi)*16 + ch*8 + ks;
            ahv[mi] = *(const uint4*)&Ah[(f*32 + lane)*4];
            alv[mi] = *(const uint4*)&Al[(f*32 + lane)*4];
          }
#pragma unroll
          for (int mi = 0; mi < 3; ++mi)
#pragma unroll
            for (int ni = 0; ni < 4; ++ni)
              mma_tf32(acc[mi*4+ni], (const uint32_t*)&ahv[mi], bh[ni]);
#pragma unroll
          for (int mi = 0; mi < 3; ++mi)
#pragma unroll
            for (int ni = 0; ni < 4; ++ni)
              mma_tf32(acc[mi*4+ni], (const uint32_t*)&ahv[mi], bl[ni]);
#pragma unroll
          for (int mi = 0; mi < 3; ++mi)
#pragma unroll
            for (int ni = 0; ni < 4; ++ni)
              mma_tf32(acc[mi*4+ni], (const uint32_t*)&alv[mi], bh[ni]);
        }
        __syncthreads();
      }
#pragma unroll
      for (int mi = 0; mi < 3; ++mi){
#pragma unroll
        for (int ni = 0; ni < 4; ++ni){
          int row0 = mtile*96 + wm*48 + mi*16 + (lane >> 2);
          int col = wn*32 + ni*8 + (lane & 3)*2;
          float* dst = g_part + ((size_t)kidx*ROWS_ + row0)*B_ + col;
          *(float2*)dst = make_float2(acc[mi*4+ni][0], acc[mi*4+ni][1]);
          *(float2*)(dst + 8*B_) = make_float2(acc[mi*4+ni][2], acc[mi*4+ni][3]);
        }
      }
    }
    bt += GRID_; gbar(bt);

    // ========== fused region ==========
    const int r = yi0 & 127;
    const int u0 = yi0 >> 7, u1 = yi1 >> 7;

    // resets for next step's slot buffers (consumed >= 2 barriers later)
    if (m < T_ && yi0 < B_*8){
      g_mid[(m+1) & 1][yi0] = 0ull;
      g_dmid[(m+1) & 1][yi0] = 0u;
    }

    // ---- Yc gate prefetch (hoisted above Yv; overlaps its loads) ----
    float A0[4], A1[4];
    if (m < T_){
#pragma unroll
      for (int g = 0; g < 4; ++g){
        size_t c0 = (size_t)(g*512 + u0)*B_ + r;
        A0[g] = g_base[c0] + __ldcg(&g_part[c0]) + __ldcg(&g_part[(size_t)ROWS_*B_ + c0])
              + __ldcg(&g_part[(size_t)2*ROWS_*B_ + c0]) + __ldcg(&g_part[(size_t)3*ROWS_*B_ + c0]);
      }
      if (v1ok){
#pragma unroll
        for (int g = 0; g < 4; ++g){
          size_t c1 = (size_t)(g*512 + u1)*B_ + r;
          A1[g] = g_base[c1] + __ldcg(&g_part[c1]) + __ldcg(&g_part[(size_t)ROWS_*B_ + c1])
                + __ldcg(&g_part[(size_t)2*ROWS_*B_ + c1]) + __ldcg(&g_part[(size_t)3*ROWS_*B_ + c1]);
        }
      }
    }

    // ---- Yv: vocab reduce + slotted argmax (148->18 deep chains) ----
    if (m >= 1){
      const int v0 = cta*7;
      if (wid < 7){
        int v = v0 + wid;
        if (v < VOCAB_){
          float bo = __ldg(bout + v);
          const float* p = g_part + (size_t)(NG_ + v)*B_;
#pragma unroll
          for (int rq = 0; rq < 4; ++rq){
            int rr2 = rq*32 + lane;
            float sum = bo + __ldcg(p + rr2)
                      + __ldcg(p + (size_t)ROWS_*B_ + rr2)
                      + __ldcg(p + (size_t)2*ROWS_*B_ + rr2)
                      + __ldcg(p + (size_t)3*ROWS_*B_ + rr2);
            Ls[wid*128 + rr2] = sum;
          }
        }
      }
      __syncthreads();
      if (m < T_ && tid < 128 && cta <= 142){
        unsigned long long best = 0ull;
        for (int vl = 0; vl < 7; ++vl){
          int v = v0 + vl;
          if (v < VOCAB_){
            unsigned long long pk = ((unsigned long long)fkey(Ls[vl*128 + tid]) << 32)
                                  | (unsigned)(VOCAB_-1 - v);
            if (pk > best) best = pk;
          }
        }
        int slot = cta & 7;
        atomicMax(&g_mid[m & 1][tid*8 + slot], best);
        __threadfence();
        atomicAdd(&g_dmid[m & 1][tid*8 + slot], 1u);
      }
    }

    // ---- Yc: spin on 8 slot counters, resolve token, cell ----
    if (m < T_){
      if (m >= 1){
        volatile unsigned* dc = (volatile unsigned*)&g_dmid[m & 1][r*8];
#pragma unroll
        for (int s = 0; s < 8; ++s){
          unsigned need = 18u - (unsigned)(s == 7);
          while (dc[s] < need) { __nanosleep(32); }
        }
        __threadfence();
      }
      unsigned long long pk = 0ull;
#pragma unroll
      for (int s = 0; s < 8; ++s){
        unsigned long long v = __ldcg(&g_mid[m & 1][r*8 + s]);
        if (v > pk) pk = v;
      }
      int tok = (VOCAB_-1) - (int)(unsigned)(pk & 0xffffffffull);
      {
        float4 ev = __ldg((const float4*)&g_E2[((size_t)tok*HID_ + u0)*4]);
        float hn;
        lstm_cell(A0[0]+ev.x, A0[1]+ev.y, A0[2]+ev.z, A0[3]+ev.w, cr0, hn);
        float hi = tf32_rd(hn);
        g_hhi[(size_t)r*HID_ + u0] = hi;
        g_hlo[(size_t)r*HID_ + u0] = tf32_rd(hn - hi);
        if (m == T_-1){
          out[OUT_H + (size_t)r*HID_ + u0] = hn;
          out[OUT_C + (size_t)r*HID_ + u0] = cr0;
        }
      }
      if (v1ok){
        float4 ev = __ldg((const float4*)&g_E2[((size_t)tok*HID_ + u1)*4]);
        float hn;
        lstm_cell(A1[0]+ev.x, A1[1]+ev.y, A1[2]+ev.z, A1[3]+ev.w, cr1, hn);
        float hi = tf32_rd(hn);
        g_hhi[(size_t)r*HID_ + u1] = hi;
        g_hlo[(size_t)r*HID_ + u1] = tf32_rd(hn - hi);
        if (m == T_-1){
          out[OUT_H + (size_t)r*HID_ + u1] = hn;
          out[OUT_C + (size_t)r*HID_ + u1] = cr1;
        }
      }
    }

    // ---- logits store (off the critical path, after cell) ----
    if (m >= 1){
      const int v0 = cta*7;
      for (int it = tid; it < 128*8; it += NTHR){
        int rr2 = it >> 3, vl = it & 7;
        int v = v0 + vl;
        if (vl < 7 && v < VOCAB_)
          out[((size_t)rr2*T_ + (m-1))*VOCAB_ + v] = Ls[vl*128 + rr2];
      }
    }
    if (m == T_) break;
    bt += GRID_; gbar(bt);
  }
}

// ---------------- launch ----------------
extern "C" void kernel_launch(void* const* d_in, const int* in_sizes, int n_in,
                              void* d_out, int out_size){
  const float* ctx  = (const float*)d_in[0];
  const float* emb  = (const float*)d_in[1];
  const float* Wih  = (const float*)d_in[2];
  const float* bih  = (const float*)d_in[3];
  const float* Whh  = (const float*)d_in[4];
  const float* bhh  = (const float*)d_in[5];
  const float* Wout = (const float*)d_in[6];
  const float* bout = (const float*)d_in[7];
  const int*   sid  = (const int*)d_in[8];
  float* out = (float*)d_out;

  cudaFuncSetAttribute(k_persist, cudaFuncAttributeMaxDynamicSharedMemorySize,
                       SMW_ * 4);

  dim3 gE(32, 16);
  k_E<<<gE, 256>>>(emb, Wih);
  k_base<<<128, 256>>>(Wih, bih, bhh, ctx);
  k_init<<<256, 256>>>(ctx, sid);
  k_persist<<<GRID_, NTHR, SMW_ * 4>>>(Whh, Wout, bout, out);
}

// round 16
// speedup vs baseline: 1.5792x; 1.5792x over previous
#include <cuda_runtime.h>
#include <math.h>
#include <stdint.h>

#define B_     128
#define HID_   512
#define NG_    2048
#define VOCAB_ 1000
#define VTOT_  3048
#define ROWS_  3072
#define T_     256
#define GRID_  148
#define NTHR   256
#define XCTAS  128           // 32 M-tiles (96 rows) x 4 K-splits

#define OUT_H  (B_*T_*VOCAB_)
#define OUT_C  (OUT_H + B_*HID_)

// ---------------- device scratch ----------------
__device__ __align__(16) float g_E2[VOCAB_*NG_];     // [v][u][4]: i,f,g,o
__device__ __align__(16) float g_base[NG_*B_];       // col-major [gatecol][r]
__device__ __align__(16) float g_hhi[B_*HID_];       // tf32-hi of h
__device__ __align__(16) float g_hlo[B_*HID_];       // tf32-lo of h
__device__ __align__(16) float g_part[4*ROWS_*B_];   // [k][row][r]
__device__ unsigned long long g_pack[2][B_];
__device__ unsigned g_done[2][B_];
__device__ unsigned g_bar;

__device__ __forceinline__ float tf32_rd(float x){
  uint32_t u; asm("cvt.rna.tf32.f32 %0, %1;" : "=r"(u) : "f"(x));
  return __uint_as_float(u);
}
__device__ __forceinline__ unsigned fkey(float x){
  unsigned u = __float_as_uint(x);
  return (u & 0x80000000u) ? ~u : (u | 0x80000000u);
}
__device__ __forceinline__ void mma_tf32(float* d, const uint32_t* a, const uint32_t* b){
  asm volatile("mma.sync.aligned.m16n8k8.row.col.f32.tf32.tf32.f32 "
    "{%0,%1,%2,%3}, {%4,%5,%6,%7}, {%8,%9}, {%0,%1,%2,%3};"
    : "+f"(d[0]), "+f"(d[1]), "+f"(d[2]), "+f"(d[3])
    : "r"(a[0]), "r"(a[1]), "r"(a[2]), "r"(a[3]), "r"(b[0]), "r"(b[1]));
}
#define DOT4(acc, a, b) acc = fmaf((a).x,(b).x, fmaf((a).y,(b).y, fmaf((a).z,(b).z, fmaf((a).w,(b).w,(acc)))))

// ---- MUFU-free transcendentals (FMA pipe only) ----
__device__ __forceinline__ float ex2f(float x){
  float xr = rintf(x);
  float f = x - xr;
  float p = 1.5252734e-5f;
  p = fmaf(p, f, 1.5403530e-4f);
  p = fmaf(p, f, 1.3333558e-3f);
  p = fmaf(p, f, 9.6181291e-3f);
  p = fmaf(p, f, 5.5504109e-2f);
  p = fmaf(p, f, 2.4022651e-1f);
  p = fmaf(p, f, 6.9314718e-1f);
  p = fmaf(p, f, 1.0f);
  return __int_as_float(__float_as_int(p) + ((int)xr << 23));
}
__device__ __forceinline__ float rcpf(float d){
  float r = __int_as_float((int)(0x7EF127EAu - (unsigned)__float_as_int(d)));
  r = r * fmaf(-d, r, 2.f);
  r = r * fmaf(-d, r, 2.f);
  r = r * fmaf(-d, r, 2.f);
  return r;
}
#define L2E 1.4426950408889634f

__device__ __forceinline__ void lstm_cell(float gi, float gf, float gg, float go,
                                          float& c, float& hn){
  gi = fminf(fmaxf(gi, -15.f), 15.f);
  gf = fminf(fmaxf(gf, -15.f), 15.f);
  gg = fminf(fmaxf(gg, -15.f), 15.f);
  go = fminf(fmaxf(go, -15.f), 15.f);
  float ei = ex2f(-L2E*gi), ef = ex2f(-L2E*gf);
  float eo = ex2f(-L2E*go), eg = ex2f(-2.f*L2E*gg);
  float di = 1.f+ei, df = 1.f+ef, dv = 1.f+eo, dg = 1.f+eg;
  float q1 = di*df, q2 = dv*dg;
  float rp = rcpf(q1*q2);
  float si = rp*df*q2;
  float sf = rp*di*q2;
  float so = rp*q1*dg;
  float tg = (1.f-eg)*(rp*q1*dv);
  float cn = fmaf(sf, c, si*tg);
  c = cn;
  float tc = fminf(fmaxf(cn, -15.f), 15.f);
  float ec = ex2f(-2.f*L2E*tc);
  hn = so * (1.f-ec) * rcpf(1.f+ec);
}

// ---------------- prologue 1: E2 = embed @ Wih_emb^T ----------------
__global__ void __launch_bounds__(256) k_E(const float* __restrict__ emb,
                                           const float* __restrict__ Wih){
  __shared__ float As[16*68], Bs[16*68];
  const int tid = threadIdx.x;
  const int tx = tid & 15, ty = tid >> 4;
  const int c0 = blockIdx.x * 64, v0 = blockIdx.y * 64;
  float acc[4][4];
#pragma unroll
  for (int i=0;i<4;++i)
#pragma unroll
    for (int j=0;j<4;++j) acc[i][j] = 0.f;

  const int rr = tid >> 2, kq = tid & 3;
  for (int kc = 0; kc < 512; kc += 16){
    int v = v0 + rr; if (v >= VOCAB_) v = VOCAB_ - 1;
    float4 a = __ldg((const float4*)(emb + (size_t)v*512 + kc + 4*kq));
    As[(4*kq+0)*68 + rr] = a.x; As[(4*kq+1)*68 + rr] = a.y;
    As[(4*kq+2)*68 + rr] = a.z; As[(4*kq+3)*68 + rr] = a.w;
    int g = c0 + rr;
    float4 b = __ldg((const float4*)(Wih + (size_t)g*1024 + 512 + kc + 4*kq));
    Bs[(4*kq+0)*68 + rr] = b.x; Bs[(4*kq+1)*68 + rr] = b.y;
    Bs[(4*kq+2)*68 + rr] = b.z; Bs[(4*kq+3)*68 + rr] = b.w;
    __syncthreads();
#pragma unroll
    for (int k = 0; k < 16; ++k){
      float4 av = *(const float4*)&As[k*68 + ty*4];
      float4 bv = *(const float4*)&Bs[k*68 + tx*4];
      float ai[4] = {av.x, av.y, av.z, av.w};
      float bj[4] = {bv.x, bv.y, bv.z, bv.w};
#pragma unroll
      for (int i=0;i<4;++i)
#pragma unroll
        for (int j=0;j<4;++j) acc[i][j] = fmaf(ai[i], bj[j], acc[i][j]);
    }
    __syncthreads();
  }
  for (int i=0;i<4;++i){
    int v = v0 + ty*4 + i;
    if (v < VOCAB_)
      for (int j=0;j<4;++j){
        int c = c0 + tx*4 + j;
        g_E2[((size_t)v*512 + (c & 511))*4 + (c >> 9)] = acc[i][j];
      }
  }
}

// ---------------- prologue 2: g_base (exact fp32) ----------------
__global__ void __launch_bounds__(256) k_base(const float* __restrict__ Wih,
                                              const float* __restrict__ bih,
                                              const float* __restrict__ bhh,
                                              const float* __restrict__ ctx){
  __shared__ float xs[128*68], wsm[16*68];
  const int tid = threadIdx.x, blk = blockIdx.x;
  const int tx = tid & 7, ty = tid >> 3, r0 = ty*4;
  const int gc0 = blk*16 + 2*tx, gc1 = gc0 + 1;
  float acc[4][2];
#pragma unroll
  for (int i=0;i<4;++i){ acc[i][0]=0.f; acc[i][1]=0.f; }

  for (int kc = 0; kc < 512; kc += 64){
    for (int p = 0; p < 8; ++p){
      int lin = tid + p*256; int r = lin >> 4, kq2 = lin & 15;
      *(float4*)&xs[r*68 + 4*kq2] = __ldg((const float4*)(ctx + (size_t)r*512 + kc + 4*kq2));
    }
    { int cc = tid >> 4, kq2 = tid & 15;
      *(float4*)&wsm[cc*68 + 4*kq2] =
        __ldg((const float4*)(Wih + (size_t)(blk*16+cc)*1024 + kc + 4*kq2)); }
    __syncthreads();
#pragma unroll
    for (int k4 = 0; k4 < 16; ++k4){
      int kl = 4*k4;
      float4 w0 = *(const float4*)&wsm[(2*tx)*68 + kl];
      float4 w1 = *(const float4*)&wsm[(2*tx+1)*68 + kl];
#pragma unroll
      for (int i=0;i<4;++i){
        float4 h4 = *(const float4*)&xs[(r0+i)*68 + kl];
        DOT4(acc[i][0], h4, w0); DOT4(acc[i][1], h4, w1);
      }
    }
    __syncthreads();
  }
  float bb0 = __ldg(bih+gc0) + __ldg(bhh+gc0);
  float bb1 = __ldg(bih+gc1) + __ldg(bhh+gc1);
  for (int i=0;i<4;++i){
    g_base[(size_t)gc0*B_ + r0+i] = acc[i][0] + bb0;
    g_base[(size_t)gc1*B_ + r0+i] = acc[i][1] + bb1;
  }
}

// ---------------- prologue 3 ----------------
__global__ void k_init(const float* __restrict__ ctx, const int* __restrict__ sid){
  int idx = blockIdx.x*blockDim.x + threadIdx.x;
  if (idx < B_*HID_){
    float x = ctx[idx];
    float hi = tf32_rd(x);
    g_hhi[idx] = hi;
    g_hlo[idx] = tf32_rd(x - hi);
  }
  if (idx < B_){
    g_pack[0][idx] = (unsigned long long)(unsigned)((VOCAB_-1) - *sid);
    g_pack[1][idx] = 0ull;
    g_done[0][idx] = 0u;
    g_done[1][idx] = 0u;
  }
  if (idx == 0) g_bar = 0u;
}

// ---------------- grid barrier ----------------
__device__ __forceinline__ void gbar(unsigned target){
  __syncthreads();
  if (threadIdx.x == 0){
    __threadfence();
    atomicAdd(&g_bar, 1u);
    while (*(volatile unsigned*)&g_bar < target) { }
    __threadfence();
  }
  __syncthreads();
}

// ---------------- persistent kernel ----------------
// smem float offsets
#define SA_H   0                 // A hi frag-packed: 96*128 = 12288
#define SA_L   12288             // A lo
#define SB_H   24576             // B hi tile [128][68] = 8704
#define SB_L   33280             // B lo tile
#define S_LS   41984             // 8*128 floats
#define SMW_   43008             // 172032 bytes

__global__ void __launch_bounds__(NTHR, 1)
k_persist(const float* __restrict__ Whh, const float* __restrict__ Wout,
          const float* __restrict__ bout, float* __restrict__ out){
  extern __shared__ float sm[];
  float* Ah = sm + SA_H;
  float* Al = sm + SA_L;
  float* Bh = sm + SB_H;
  float* Bl = sm + SB_L;
  float* Ls = sm + S_LS;

  const int cta = blockIdx.x, tid = threadIdx.x;
  const int wid = tid >> 5, lane = tid & 31;
  const bool isX = (cta < XCTAS);
  const int mtile = cta >> 2, kidx = cta & 3, kbase = kidx*128;
  const int wm = wid >> 2, wn = wid & 3;          // warp tile 48M x 32N

  // ---- stage A (weights hi/lo, fragment-packed) once ----
  if (isX){
    for (int lin = tid; lin < 3072; lin += NTHR){
      int ml = lin >> 5, q = lin & 31;
      int gm = mtile*96 + ml;
      float4 w = make_float4(0.f,0.f,0.f,0.f);
      if (gm < NG_)        w = __ldg((const float4*)(Whh  + (size_t)gm*HID_ + kbase + q*4));
      else if (gm < VTOT_) w = __ldg((const float4*)(Wout + (size_t)(gm-NG_)*HID_ + kbase + q*4));
      int f = (ml >> 4)*16 + (q >> 1);
      int ofs = f*128 + (ml & 7)*16 + ((ml >> 3) & 1) + 2*(q & 1);
      float hi;
      hi = tf32_rd(w.x); Ah[ofs+ 0] = hi; Al[ofs+ 0] = tf32_rd(w.x - hi);
      hi = tf32_rd(w.y); Ah[ofs+ 4] = hi; Al[ofs+ 4] = tf32_rd(w.y - hi);
      hi = tf32_rd(w.z); Ah[ofs+ 8] = hi; Al[ofs+ 8] = tf32_rd(w.z - hi);
      hi = tf32_rd(w.w); Ah[ofs+12] = hi; Al[ofs+12] = tf32_rd(w.w - hi);
    }
  }
  __syncthreads();

  float cr0 = 0.f, cr1 = 0.f;
  const int yi0 = cta*NTHR + tid;                 // < 37888
  const int yi1 = yi0 + GRID_*NTHR;               // yi1 & 127 == yi0 & 127
  const bool v1ok = (yi1 < B_*HID_);

  unsigned bt = 0;
  for (int m = 0; m <= T_; ++m){
    // ================ phase X: 3xTF32 mma.sync ================
    if (isX){
      float acc[12][4];
#pragma unroll
      for (int i=0;i<12;++i)
#pragma unroll
        for (int j=0;j<4;++j) acc[i][j] = 0.f;

      for (int ch = 0; ch < 2; ++ch){
        for (int lin = tid; lin < 2048; lin += NTHR){
          int r = lin >> 4, q = lin & 15;
          float4 h = __ldcg((const float4*)(g_hhi + (size_t)r*HID_ + kbase + ch*64 + q*4));
          float4 l = __ldcg((const float4*)(g_hlo + (size_t)r*HID_ + kbase + ch*64 + q*4));
          *(float4*)&Bh[r*68 + q*4] = h;
          *(float4*)&Bl[r*68 + q*4] = l;
        }
        __syncthreads();
#pragma unroll 2
        for (int ks = 0; ks < 8; ++ks){
          uint32_t bh[4][2], bl[4][2];
          int kk = ks*8 + (lane & 3);
#pragma unroll
          for (int ni = 0; ni < 4; ++ni){
            int n = wn*32 + ni*8 + (lane >> 2);
            bh[ni][0] = __float_as_uint(Bh[n*68 + kk]);
            bh[ni][1] = __float_as_uint(Bh[n*68 + kk + 4]);
            bl[ni][0] = __float_as_uint(Bl[n*68 + kk]);
            bl[ni][1] = __float_as_uint(Bl[n*68 + kk + 4]);
          }
          uint4 ahv[3], alv[3];
#pragma unroll
          for (int mi = 0; mi < 3; ++mi){
            int f = (wm*3 + mi)*16 + ch*8 + ks;
            ahv[mi] = *(const uint4*)&Ah[(f*32 + lane)*4];
            alv[mi] = *(const uint4*)&Al[(f*32 + lane)*4];
          }
#pragma unroll
          for (int mi = 0; mi < 3; ++mi)
#pragma unroll
            for (int ni = 0; ni < 4; ++ni)
              mma_tf32(acc[mi*4+ni], (const uint32_t*)&ahv[mi], bh[ni]);
#pragma unroll
          for (int mi = 0; mi < 3; ++mi)
#pragma unroll
            for (int ni = 0; ni < 4; ++ni)
              mma_tf32(acc[mi*4+ni], (const uint32_t*)&ahv[mi], bl[ni]);
#pragma unroll
          for (int mi = 0; mi < 3; ++mi)
#pragma unroll
            for (int ni = 0; ni < 4; ++ni)
              mma_tf32(acc[mi*4+ni], (const uint32_t*)&alv[mi], bh[ni]);
        }
        __syncthreads();
      }
#pragma unroll
      for (int mi = 0; mi < 3; ++mi){
#pragma unroll
        for (int ni = 0; ni < 4; ++ni){
          int row0 = mtile*96 + wm*48 + mi*16 + (lane >> 2);
          int col = wn*32 + ni*8 + (lane & 3)*2;
          float* dst = g_part + ((size_t)kidx*ROWS_ + row0)*B_ + col;
          *(float2*)dst = make_float2(acc[mi*4+ni][0], acc[mi*4+ni][1]);
          *(float2*)(dst + 8*B_) = make_float2(acc[mi*4+ni][2], acc[mi*4+ni][3]);
        }
      }
    }
    bt += GRID_; gbar(bt);

    // ========== fused region ==========
    const int r = yi0 & 127;
    const int u0 = yi0 >> 7, u1 = yi1 >> 7;

    // resets for next step's buffers (consumed >= 2 barriers later)
    if (m < T_ && yi0 < B_){
      g_pack[(m+1) & 1][yi0] = 0ull;
      g_done[(m+1) & 1][yi0] = 0u;
    }

    // ---- Yc gate prefetch (hoisted above Yv; overlaps its loads) ----
    float A0[4], A1[4];
    if (m < T_){
#pragma unroll
      for (int g = 0; g < 4; ++g){
        size_t c0 = (size_t)(g*512 + u0)*B_ + r;
        A0[g] = g_base[c0] + __ldcg(&g_part[c0]) + __ldcg(&g_part[(size_t)ROWS_*B_ + c0])
              + __ldcg(&g_part[(size_t)2*ROWS_*B_ + c0]) + __ldcg(&g_part[(size_t)3*ROWS_*B_ + c0]);
      }
      if (v1ok){
#pragma unroll
        for (int g = 0; g < 4; ++g){
          size_t c1 = (size_t)(g*512 + u1)*B_ + r;
          A1[g] = g_base[c1] + __ldcg(&g_part[c1]) + __ldcg(&g_part[(size_t)ROWS_*B_ + c1])
                + __ldcg(&g_part[(size_t)2*ROWS_*B_ + c1]) + __ldcg(&g_part[(size_t)3*ROWS_*B_ + c1]);
        }
      }
    }

    // ---- Yv: vocab reduce + argmax + signal (R14-proven chains) ----
    if (m >= 1){
      const int v0 = cta*7;
      if (wid < 7){
        int v = v0 + wid;
        if (v < VOCAB_){
          float bo = __ldg(bout + v);
          const float* p = g_part + (size_t)(NG_ + v)*B_;
#pragma unroll
          for (int rq = 0; rq < 4; ++rq){
            int rr2 = rq*32 + lane;
            float sum = bo + __ldcg(p + rr2)
                      + __ldcg(p + (size_t)ROWS_*B_ + rr2)
                      + __ldcg(p + (size_t)2*ROWS_*B_ + rr2)
                      + __ldcg(p + (size_t)3*ROWS_*B_ + rr2);
            Ls[wid*128 + rr2] = sum;
          }
        }
      }
      __syncthreads();
      if (m < T_ && tid < 128){
        unsigned long long best = 0ull;
        for (int vl = 0; vl < 7; ++vl){
          int v = v0 + vl;
          if (v < VOCAB_){
            unsigned long long pk = ((unsigned long long)fkey(Ls[vl*128 + tid]) << 32)
                                  | (unsigned)(VOCAB_-1 - v);
            if (pk > best) best = pk;
          }
        }
        if (best) atomicMax(&g_pack[m & 1][tid], best);
        __threadfence();
        atomicAdd(&g_done[m & 1][tid], 1u);
      }
    }

    // ---- Yc: spin on row, resolve token, cell ----
    if (m < T_){
      if (m >= 1){
        volatile unsigned* dc = (volatile unsigned*)g_done[m & 1];
        while (dc[r] < (unsigned)GRID_) { __nanosleep(32); }
        __threadfence();
      }
      unsigned long long p = __ldcg(&g_pack[m & 1][r]);
      int tok = (VOCAB_-1) - (int)(unsigned)(p & 0xffffffffull);
      {
        float4 ev = __ldg((const float4*)&g_E2[((size_t)tok*HID_ + u0)*4]);
        float hn;
        lstm_cell(A0[0]+ev.x, A0[1]+ev.y, A0[2]+ev.z, A0[3]+ev.w, cr0, hn);
        float hi = tf32_rd(hn);
        g_hhi[(size_t)r*HID_ + u0] = hi;
        g_hlo[(size_t)r*HID_ + u0] = tf32_rd(hn - hi);
        if (m == T_-1){
          out[OUT_H + (size_t)r*HID_ + u0] = hn;
          out[OUT_C + (size_t)r*HID_ + u0] = cr0;
        }
      }
      if (v1ok){
        float4 ev = __ldg((const float4*)&g_E2[((size_t)tok*HID_ + u1)*4]);
        float hn;
        lstm_cell(A1[0]+ev.x, A1[1]+ev.y, A1[2]+ev.z, A1[3]+ev.w, cr1, hn);
        float hi = tf32_rd(hn);
        g_hhi[(size_t)r*HID_ + u1] = hi;
        g_hlo[(size_t)r*HID_ + u1] = tf32_rd(hn - hi);
        if (m == T_-1){
          out[OUT_H + (size_t)r*HID_ + u1] = hn;
          out[OUT_C + (size_t)r*HID_ + u1] = cr1;
        }
      }
    }

    // ---- logits store (off the critical path, after cell) ----
    if (m >= 1){
      const int v0 = cta*7;
      for (int it = tid; it < 128*8; it += NTHR){
        int rr2 = it >> 3, vl = it & 7;
        int v = v0 + vl;
        if (vl < 7 && v < VOCAB_)
          out[((size_t)rr2*T_ + (m-1))*VOCAB_ + v] = Ls[vl*128 + rr2];
      }
    }
    if (m == T_) break;
    bt += GRID_; gbar(bt);
  }
}

// ---------------- launch ----------------
extern "C" void kernel_launch(void* const* d_in, const int* in_sizes, int n_in,
                              void* d_out, int out_size){
  const float* ctx  = (const float*)d_in[0];
  const float* emb  = (const float*)d_in[1];
  const float* Wih  = (const float*)d_in[2];
  const float* bih  = (const float*)d_in[3];
  const float* Whh  = (const float*)d_in[4];
  const float* bhh  = (const float*)d_in[5];
  const float* Wout = (const float*)d_in[6];
  const float* bout = (const float*)d_in[7];
  const int*   sid  = (const int*)d_in[8];
  float* out = (float*)d_out;

  cudaFuncSetAttribute(k_persist, cudaFuncAttributeMaxDynamicSharedMemorySize,
                       SMW_ * 4);

  dim3 gE(32, 16);
  k_E<<<gE, 256>>>(emb, Wih);
  k_base<<<128, 256>>>(Wih, bih, bhh, ctx);
  k_init<<<256, 256>>>(ctx, sid);
  k_persist<<<GRID_, NTHR, SMW_ * 4>>>(Whh, Wout, bout, out);
}

// round 17
// speedup vs baseline: 1.7406x; 1.1022x over previous
#include <cuda_runtime.h>
#include <math.h>
#include <stdint.h>

#define B_     128
#define HID_   512
#define NG_    2048
#define VOCAB_ 1000
#define VTOT_  3048
#define ROWS_  3072
#define T_     256
#define GRID_  148
#define NTHR   256
#define XCTAS  128           // 32 M-tiles (96 rows) x 4 K-splits

#define OUT_H  (B_*T_*VOCAB_)
#define OUT_C  (OUT_H + B_*HID_)

// ---------------- device scratch ----------------
__device__ __align__(16) float g_E2[VOCAB_*NG_];     // [v][u][4]: i,f,g,o
__device__ __align__(16) float g_base[NG_*B_];       // col-major [gatecol][r]
__device__ __align__(16) float g_hhi[B_*HID_];       // tf32-hi of h
__device__ __align__(16) float g_hlo[B_*HID_];       // tf32-lo of h
__device__ __align__(16) float g_part[4*ROWS_*B_];   // [k][row][r]
__device__ unsigned long long g_pack[2][B_];
__device__ unsigned g_done[2][B_];
__device__ unsigned g_bar;

__device__ __forceinline__ float tf32_rd(float x){
  uint32_t u; asm("cvt.rna.tf32.f32 %0, %1;" : "=r"(u) : "f"(x));
  return __uint_as_float(u);
}
__device__ __forceinline__ unsigned fkey(float x){
  unsigned u = __float_as_uint(x);
  return (u & 0x80000000u) ? ~u : (u | 0x80000000u);
}
__device__ __forceinline__ void mma_tf32(float* d, const uint32_t* a, const uint32_t* b){
  asm volatile("mma.sync.aligned.m16n8k8.row.col.f32.tf32.tf32.f32 "
    "{%0,%1,%2,%3}, {%4,%5,%6,%7}, {%8,%9}, {%0,%1,%2,%3};"
    : "+f"(d[0]), "+f"(d[1]), "+f"(d[2]), "+f"(d[3])
    : "r"(a[0]), "r"(a[1]), "r"(a[2]), "r"(a[3]), "r"(b[0]), "r"(b[1]));
}
#define DOT4(acc, a, b) acc = fmaf((a).x,(b).x, fmaf((a).y,(b).y, fmaf((a).z,(b).z, fmaf((a).w,(b).w,(acc)))))

// ---- MUFU-free transcendentals (FMA pipe only) ----
__device__ __forceinline__ float ex2f(float x){
  float xr = rintf(x);
  float f = x - xr;
  float p = 1.5252734e-5f;
  p = fmaf(p, f, 1.5403530e-4f);
  p = fmaf(p, f, 1.3333558e-3f);
  p = fmaf(p, f, 9.6181291e-3f);
  p = fmaf(p, f, 5.5504109e-2f);
  p = fmaf(p, f, 2.4022651e-1f);
  p = fmaf(p, f, 6.9314718e-1f);
  p = fmaf(p, f, 1.0f);
  return __int_as_float(__float_as_int(p) + ((int)xr << 23));
}
__device__ __forceinline__ float rcpf(float d){
  float r = __int_as_float((int)(0x7EF127EAu - (unsigned)__float_as_int(d)));
  r = r * fmaf(-d, r, 2.f);
  r = r * fmaf(-d, r, 2.f);
  r = r * fmaf(-d, r, 2.f);
  return r;
}
#define L2E 1.4426950408889634f

__device__ __forceinline__ void lstm_cell(float gi, float gf, float gg, float go,
                                          float& c, float& hn){
  gi = fminf(fmaxf(gi, -15.f), 15.f);
  gf = fminf(fmaxf(gf, -15.f), 15.f);
  gg = fminf(fmaxf(gg, -15.f), 15.f);
  go = fminf(fmaxf(go, -15.f), 15.f);
  float ei = ex2f(-L2E*gi), ef = ex2f(-L2E*gf);
  float eo = ex2f(-L2E*go), eg = ex2f(-2.f*L2E*gg);
  float di = 1.f+ei, df = 1.f+ef, dv = 1.f+eo, dg = 1.f+eg;
  float q1 = di*df, q2 = dv*dg;
  float rp = rcpf(q1*q2);
  float si = rp*df*q2;
  float sf = rp*di*q2;
  float so = rp*q1*dg;
  float tg = (1.f-eg)*(rp*q1*dv);
  float cn = fmaf(sf, c, si*tg);
  c = cn;
  float tc = fminf(fmaxf(cn, -15.f), 15.f);
  float ec = ex2f(-2.f*L2E*tc);
  hn = so * (1.f-ec) * rcpf(1.f+ec);
}

// ---------------- prologue 1: E2 = embed @ Wih_emb^T ----------------
__global__ void __launch_bounds__(256) k_E(const float* __restrict__ emb,
                                           const float* __restrict__ Wih){
  __shared__ float As[16*68], Bs[16*68];
  const int tid = threadIdx.x;
  const int tx = tid & 15, ty = tid >> 4;
  const int c0 = blockIdx.x * 64, v0 = blockIdx.y * 64;
  float acc[4][4];
#pragma unroll
  for (int i=0;i<4;++i)
#pragma unroll
    for (int j=0;j<4;++j) acc[i][j] = 0.f;

  const int rr = tid >> 2, kq = tid & 3;
  for (int kc = 0; kc < 512; kc += 16){
    int v = v0 + rr; if (v >= VOCAB_) v = VOCAB_ - 1;
    float4 a = __ldg((const float4*)(emb + (size_t)v*512 + kc + 4*kq));
    As[(4*kq+0)*68 + rr] = a.x; As[(4*kq+1)*68 + rr] = a.y;
    As[(4*kq+2)*68 + rr] = a.z; As[(4*kq+3)*68 + rr] = a.w;
    int g = c0 + rr;
    float4 b = __ldg((const float4*)(Wih + (size_t)g*1024 + 512 + kc + 4*kq));
    Bs[(4*kq+0)*68 + rr] = b.x; Bs[(4*kq+1)*68 + rr] = b.y;
    Bs[(4*kq+2)*68 + rr] = b.z; Bs[(4*kq+3)*68 + rr] = b.w;
    __syncthreads();
#pragma unroll
    for (int k = 0; k < 16; ++k){
      float4 av = *(const float4*)&As[k*68 + ty*4];
      float4 bv = *(const float4*)&Bs[k*68 + tx*4];
      float ai[4] = {av.x, av.y, av.z, av.w};
      float bj[4] = {bv.x, bv.y, bv.z, bv.w};
#pragma unroll
      for (int i=0;i<4;++i)
#pragma unroll
        for (int j=0;j<4;++j) acc[i][j] = fmaf(ai[i], bj[j], acc[i][j]);
    }
    __syncthreads();
  }
  for (int i=0;i<4;++i){
    int v = v0 + ty*4 + i;
    if (v < VOCAB_)
      for (int j=0;j<4;++j){
        int c = c0 + tx*4 + j;
        g_E2[((size_t)v*512 + (c & 511))*4 + (c >> 9)] = acc[i][j];
      }
  }
}

// ---------------- prologue 2: g_base (exact fp32) ----------------
__global__ void __launch_bounds__(256) k_base(const float* __restrict__ Wih,
                                              const float* __restrict__ bih,
                                              const float* __restrict__ bhh,
                                              const float* __restrict__ ctx){
  __shared__ float xs[128*68], wsm[16*68];
  const int tid = threadIdx.x, blk = blockIdx.x;
  const int tx = tid & 7, ty = tid >> 3, r0 = ty*4;
  const int gc0 = blk*16 + 2*tx, gc1 = gc0 + 1;
  float acc[4][2];
#pragma unroll
  for (int i=0;i<4;++i){ acc[i][0]=0.f; acc[i][1]=0.f; }

  for (int kc = 0; kc < 512; kc += 64){
    for (int p = 0; p < 8; ++p){
      int lin = tid + p*256; int r = lin >> 4, kq2 = lin & 15;
      *(float4*)&xs[r*68 + 4*kq2] = __ldg((const float4*)(ctx + (size_t)r*512 + kc + 4*kq2));
    }
    { int cc = tid >> 4, kq2 = tid & 15;
      *(float4*)&wsm[cc*68 + 4*kq2] =
        __ldg((const float4*)(Wih + (size_t)(blk*16+cc)*1024 + kc + 4*kq2)); }
    __syncthreads();
#pragma unroll
    for (int k4 = 0; k4 < 16; ++k4){
      int kl = 4*k4;
      float4 w0 = *(const float4*)&wsm[(2*tx)*68 + kl];
      float4 w1 = *(const float4*)&wsm[(2*tx+1)*68 + kl];
#pragma unroll
      for (int i=0;i<4;++i){
        float4 h4 = *(const float4*)&xs[(r0+i)*68 + kl];
        DOT4(acc[i][0], h4, w0); DOT4(acc[i][1], h4, w1);
      }
    }
    __syncthreads();
  }
  float bb0 = __ldg(bih+gc0) + __ldg(bhh+gc0);
  float bb1 = __ldg(bih+gc1) + __ldg(bhh+gc1);
  for (int i=0;i<4;++i){
    g_base[(size_t)gc0*B_ + r0+i] = acc[i][0] + bb0;
    g_base[(size_t)gc1*B_ + r0+i] = acc[i][1] + bb1;
  }
}

// ---------------- prologue 3 ----------------
__global__ void k_init(const float* __restrict__ ctx, const int* __restrict__ sid){
  int idx = blockIdx.x*blockDim.x + threadIdx.x;
  if (idx < B_*HID_){
    float x = ctx[idx];
    float hi = tf32_rd(x);
    g_hhi[idx] = hi;
    g_hlo[idx] = tf32_rd(x - hi);
  }
  if (idx < B_){
    g_pack[0][idx] = (unsigned long long)(unsigned)((VOCAB_-1) - *sid);
    g_pack[1][idx] = 0ull;
    g_done[0][idx] = 0u;
    g_done[1][idx] = 0u;
  }
  if (idx == 0) g_bar = 0u;
}

// ---------------- grid barrier ----------------
__device__ __forceinline__ void gbar(unsigned target){
  __syncthreads();
  if (threadIdx.x == 0){
    __threadfence();
    atomicAdd(&g_bar, 1u);
    while (*(volatile unsigned*)&g_bar < target) { }
    __threadfence();
  }
  __syncthreads();
}

// ---------------- persistent kernel ----------------
// smem float offsets
#define SA_H     0                       // A hi frag-packed: 96*128 = 12288
#define SA_L     12288                   // A lo
#define SBH(s)   (24576 + (s)*9216)      // B hi slot [128][36]
#define SBL(s)   (24576 + (s)*9216 + 4608)
#define S_LS     43008                   // 8*128 floats
#define SMW_     44032                   // 176128 bytes

__global__ void __launch_bounds__(NTHR, 1)
k_persist(const float* __restrict__ Whh, const float* __restrict__ Wout,
          const float* __restrict__ bout, float* __restrict__ out){
  extern __shared__ float sm[];
  float* Ah = sm + SA_H;
  float* Al = sm + SA_L;
  float* Ls = sm + S_LS;

  const int cta = blockIdx.x, tid = threadIdx.x;
  const int wid = tid >> 5, lane = tid & 31;
  const bool isX = (cta < XCTAS);
  const int mtile = cta >> 2, kidx = cta & 3, kbase = kidx*128;
  const int wm = wid >> 2, wn = wid & 3;          // warp tile 48M x 32N

  // ---- stage A (weights hi/lo, fragment-packed) once ----
  if (isX){
    for (int lin = tid; lin < 3072; lin += NTHR){
      int ml = lin >> 5, q = lin & 31;
      int gm = mtile*96 + ml;
      float4 w = make_float4(0.f,0.f,0.f,0.f);
      if (gm < NG_)        w = __ldg((const float4*)(Whh  + (size_t)gm*HID_ + kbase + q*4));
      else if (gm < VTOT_) w = __ldg((const float4*)(Wout + (size_t)(gm-NG_)*HID_ + kbase + q*4));
      int f = (ml >> 4)*16 + (q >> 1);
      int ofs = f*128 + (ml & 7)*16 + ((ml >> 3) & 1) + 2*(q & 1);
      float hi;
      hi = tf32_rd(w.x); Ah[ofs+ 0] = hi; Al[ofs+ 0] = tf32_rd(w.x - hi);
      hi = tf32_rd(w.y); Ah[ofs+ 4] = hi; Al[ofs+ 4] = tf32_rd(w.y - hi);
      hi = tf32_rd(w.z); Ah[ofs+ 8] = hi; Al[ofs+ 8] = tf32_rd(w.z - hi);
      hi = tf32_rd(w.w); Ah[ofs+12] = hi; Al[ofs+12] = tf32_rd(w.w - hi);
    }
  }
  __syncthreads();

  float cr0 = 0.f, cr1 = 0.f;
  const int yi0 = cta*NTHR + tid;                 // < 37888
  const int yi1 = yi0 + GRID_*NTHR;               // yi1 & 127 == yi0 & 127
  const bool v1ok = (yi1 < B_*HID_);

  unsigned bt = 0;
  for (int m = 0; m <= T_; ++m){
    // ================ phase X: 3xTF32 mma.sync, pipelined staging ======
    if (isX){
      float acc[12][4];
#pragma unroll
      for (int i=0;i<12;++i)
#pragma unroll
        for (int j=0;j<4;++j) acc[i][j] = 0.f;

      float4 rh[4], rl[4];
      const int sr = tid >> 3, sq = (tid & 7)*4;   // wrong for multi-p; use per-p below
      (void)sr; (void)sq;
      // preload chunk 0
#pragma unroll
      for (int p = 0; p < 4; ++p){
        int lin = tid + p*NTHR; int r = lin >> 3, q = lin & 7;
        rh[p] = __ldcg((const float4*)(g_hhi + (size_t)r*HID_ + kbase + q*4));
        rl[p] = __ldcg((const float4*)(g_hlo + (size_t)r*HID_ + kbase + q*4));
      }
#pragma unroll
      for (int p = 0; p < 4; ++p){
        int lin = tid + p*NTHR; int r = lin >> 3, q = lin & 7;
        *(float4*)&sm[SBH(0) + r*36 + q*4] = rh[p];
        *(float4*)&sm[SBL(0) + r*36 + q*4] = rl[p];
      }
      __syncthreads();

      for (int cc = 0; cc < 4; ++cc){
        const int cur = cc & 1;
        // issue loads for chunk cc+1 (land under the MMAs below)
        if (cc < 3){
          const int ko = kbase + (cc+1)*32;
#pragma unroll
          for (int p = 0; p < 4; ++p){
            int lin = tid + p*NTHR; int r = lin >> 3, q = lin & 7;
            rh[p] = __ldcg((const float4*)(g_hhi + (size_t)r*HID_ + ko + q*4));
            rl[p] = __ldcg((const float4*)(g_hlo + (size_t)r*HID_ + ko + q*4));
          }
        }
        const float* Bhp = sm + SBH(cur);
        const float* Blp = sm + SBL(cur);
#pragma unroll
        for (int ksl = 0; ksl < 4; ++ksl){
          uint32_t bh[4][2], bl[4][2];
          int kk = ksl*8 + (lane & 3);
#pragma unroll
          for (int ni = 0; ni < 4; ++ni){
            int n = wn*32 + ni*8 + (lane >> 2);
            bh[ni][0] = __float_as_uint(Bhp[n*36 + kk]);
            bh[ni][1] = __float_as_uint(Bhp[n*36 + kk + 4]);
            bl[ni][0] = __float_as_uint(Blp[n*36 + kk]);
            bl[ni][1] = __float_as_uint(Blp[n*36 + kk + 4]);
          }
          uint4 ahv[3], alv[3];
#pragma unroll
          for (int mi = 0; mi < 3; ++mi){
            int f = (wm*3 + mi)*16 + cc*4 + ksl;
            ahv[mi] = *(const uint4*)&Ah[(f*32 + lane)*4];
            alv[mi] = *(const uint4*)&Al[(f*32 + lane)*4];
          }
#pragma unroll
          for (int mi = 0; mi < 3; ++mi)
#pragma unroll
            for (int ni = 0; ni < 4; ++ni)
              mma_tf32(acc[mi*4+ni], (const uint32_t*)&ahv[mi], bh[ni]);
#pragma unroll
          for (int mi = 0; mi < 3; ++mi)
#pragma unroll
            for (int ni = 0; ni < 4; ++ni)
              mma_tf32(acc[mi*4+ni], (const uint32_t*)&ahv[mi], bl[ni]);
#pragma unroll
          for (int mi = 0; mi < 3; ++mi)
#pragma unroll
            for (int ni = 0; ni < 4; ++ni)
              mma_tf32(acc[mi*4+ni], (const uint32_t*)&alv[mi], bh[ni]);
        }
        // store next chunk into the other slot, then sync
        if (cc < 3){
#pragma unroll
          for (int p = 0; p < 4; ++p){
            int lin = tid + p*NTHR; int r = lin >> 3, q = lin & 7;
            *(float4*)&sm[SBH(cur ^ 1) + r*36 + q*4] = rh[p];
            *(float4*)&sm[SBL(cur ^ 1) + r*36 + q*4] = rl[p];
          }
        }
        __syncthreads();
      }
#pragma unroll
      for (int mi = 0; mi < 3; ++mi){
#pragma unroll
        for (int ni = 0; ni < 4; ++ni){
          int row0 = mtile*96 + wm*48 + mi*16 + (lane >> 2);
          int col = wn*32 + ni*8 + (lane & 3)*2;
          float* dst = g_part + ((size_t)kidx*ROWS_ + row0)*B_ + col;
          *(float2*)dst = make_float2(acc[mi*4+ni][0], acc[mi*4+ni][1]);
          *(float2*)(dst + 8*B_) = make_float2(acc[mi*4+ni][2], acc[mi*4+ni][3]);
        }
      }
    }
    bt += GRID_; gbar(bt);

    // ========== fused region (R14 order) ==========
    if (m < T_ && yi0 < B_){
      g_pack[(m+1) & 1][yi0] = 0ull;
      g_done[(m+1) & 1][yi0] = 0u;
    }
    if (m >= 1){
      const int v0 = cta*7;
      if (wid < 7){
        int v = v0 + wid;
        if (v < VOCAB_){
          float bo = __ldg(bout + v);
          const float* p = g_part + (size_t)(NG_ + v)*B_;
#pragma unroll
          for (int rq = 0; rq < 4; ++rq){
            int rr2 = rq*32 + lane;
            float sum = bo + __ldcg(p + rr2)
                      + __ldcg(p + (size_t)ROWS_*B_ + rr2)
                      + __ldcg(p + (size_t)2*ROWS_*B_ + rr2)
                      + __ldcg(p + (size_t)3*ROWS_*B_ + rr2);
            Ls[wid*128 + rr2] = sum;
          }
        }
      }
      __syncthreads();
      if (m < T_ && tid < 128){
        unsigned long long best = 0ull;
        for (int vl = 0; vl < 7; ++vl){
          int v = v0 + vl;
          if (v < VOCAB_){
            unsigned long long pk = ((unsigned long long)fkey(Ls[vl*128 + tid]) << 32)
                                  | (unsigned)(VOCAB_-1 - v);
            if (pk > best) best = pk;
          }
        }
        if (best) atomicMax(&g_pack[m & 1][tid], best);
        __threadfence();
        atomicAdd(&g_done[m & 1][tid], 1u);
      }
      for (int it = tid; it < 128*8; it += NTHR){
        int rr2 = it >> 3, vl = it & 7;
        int v = v0 + vl;
        if (vl < 7 && v < VOCAB_)
          out[((size_t)rr2*T_ + (m-1))*VOCAB_ + v] = Ls[vl*128 + rr2];
      }
    }
    if (m == T_) break;

    // ---- Yc: prefetch token-independent gates, spin, cell ----
    {
      const int r = yi0 & 127;
      const int u0 = yi0 >> 7, u1 = yi1 >> 7;
      float A0[4], A1[4];
#pragma unroll
      for (int g = 0; g < 4; ++g){
        size_t c0 = (size_t)(g*512 + u0)*B_ + r;
        A0[g] = g_base[c0] + __ldcg(&g_part[c0]) + __ldcg(&g_part[(size_t)ROWS_*B_ + c0])
              + __ldcg(&g_part[(size_t)2*ROWS_*B_ + c0]) + __ldcg(&g_part[(size_t)3*ROWS_*B_ + c0]);
      }
      if (v1ok){
#pragma unroll
        for (int g = 0; g < 4; ++g){
          size_t c1 = (size_t)(g*512 + u1)*B_ + r;
          A1[g] = g_base[c1] + __ldcg(&g_part[c1]) + __ldcg(&g_part[(size_t)ROWS_*B_ + c1])
                + __ldcg(&g_part[(size_t)2*ROWS_*B_ + c1]) + __ldcg(&g_part[(size_t)3*ROWS_*B_ + c1]);
        }
      }
      if (m >= 1){
        volatile unsigned* dc = (volatile unsigned*)g_done[m & 1];
        while (dc[r] < (unsigned)GRID_) { __nanosleep(32); }
        __threadfence();
      }
      unsigned long long p = __ldcg(&g_pack[m & 1][r]);
      int tok = (VOCAB_-1) - (int)(unsigned)(p & 0xffffffffull);
      {
        float4 ev = __ldg((const float4*)&g_E2[((size_t)tok*HID_ + u0)*4]);
        float hn;
        lstm_cell(A0[0]+ev.x, A0[1]+ev.y, A0[2]+ev.z, A0[3]+ev.w, cr0, hn);
        float hi = tf32_rd(hn);
        g_hhi[(size_t)r*HID_ + u0] = hi;
        g_hlo[(size_t)r*HID_ + u0] = tf32_rd(hn - hi);
        if (m == T_-1){
          out[OUT_H + (size_t)r*HID_ + u0] = hn;
          out[OUT_C + (size_t)r*HID_ + u0] = cr0;
        }
      }
      if (v1ok){
        float4 ev = __ldg((const float4*)&g_E2[((size_t)tok*HID_ + u1)*4]);
        float hn;
        lstm_cell(A1[0]+ev.x, A1[1]+ev.y, A1[2]+ev.z, A1[3]+ev.w, cr1, hn);
        float hi = tf32_rd(hn);
        g_hhi[(size_t)r*HID_ + u1] = hi;
        g_hlo[(size_t)r*HID_ + u1] = tf32_rd(hn - hi);
        if (m == T_-1){
          out[OUT_H + (size_t)r*HID_ + u1] = hn;
          out[OUT_C + (size_t)r*HID_ + u1] = cr1;
        }
      }
    }
    bt += GRID_; gbar(bt);
  }
}

// ---------------- launch ----------------
extern "C" void kernel_launch(void* const* d_in, const int* in_sizes, int n_in,
                              void* d_out, int out_size){
  const float* ctx  = (const float*)d_in[0];
  const float* emb  = (const float*)d_in[1];
  const float* Wih  = (const float*)d_in[2];
  const float* bih  = (const float*)d_in[3];
  const float* Whh  = (const float*)d_in[4];
  const float* bhh  = (const float*)d_in[5];
  const float* Wout = (const float*)d_in[6];
  const float* bout = (const float*)d_in[7];
  const int*   sid  = (const int*)d_in[8];
  float* out = (float*)d_out;

  cudaFuncSetAttribute(k_persist, cudaFuncAttributeMaxDynamicSharedMemorySize,
                       SMW_ * 4);

  dim3 gE(32, 16);
  k_E<<<gE, 256>>>(emb, Wih);
  k_base<<<128, 256>>>(Wih, bih, bhh, ctx);
  k_init<<<256, 256>>>(ctx, sid);
  k_persist<<<GRID_, NTHR, SMW_ * 4>>>(Whh, Wout, bout, out);
}